// round 10
// baseline (speedup 1.0000x reference)
#include <cuda_runtime.h>
#include <cstdint>
#include <math.h>

// ---------------- problem constants ----------------
#define BB   4
#define PP   2048
#define DD   1024
#define HH   16
#define KVH  8
#define HDIM 64
#define FFN  4096
#define NE   16
#define FE   256
#define NTOK (BB*PP)          // 8192

// ---------------- scratch (no allocs allowed) ----------------
__device__ float g_h   [(size_t)NTOK*DD];
__device__ float g_q   [(size_t)NTOK*HH*HDIM];
__device__ float g_k   [(size_t)NTOK*KVH*HDIM];
__device__ float g_v   [(size_t)NTOK*KVH*HDIM];
__device__ float g_att [(size_t)NTOK*DD];
__device__ float g_x2  [(size_t)NTOK*DD];
__device__ float g_h2  [(size_t)NTOK*DD];
__device__ float g_gate[(size_t)NTOK*FFN];
__device__ float g_up  [(size_t)NTOK*FFN];
__device__ float g_eg  [(size_t)NTOK*NE*FE];
__device__ float g_eu  [(size_t)NTOK*NE*FE];
__device__ float g_tmp [(size_t)NTOK*DD];

// =================== tf32 mma.sync GEMM, cp.async 3-stage ===================
// C[M x N](+z*sC) = A[M x K] @ (B + z*sB)[K x N]   (lda==K, ldb==N)
// CTA tile 128x128, K staged by 32, 3-stage cp.async, 8 warps (2x4),
// warp tile 64x32, mma.m16n8k8.tf32, cvt.rna post-LDS.
// EPI: 0 none, 1 +bias[col], 2 +res, 3 silu(acc)*res, 4 silu(acc)*res*mask[r*NE+z]
#define ASTR 36                         // A smem row stride (floats), [m][k]: bank=4*gid+tig, conflict-free
#define BSTR 136                        // B smem row stride (floats), [k][n]: bank=8*tig+gid, conflict-free
#define ASZ  (128*ASTR)                 // 4608 floats
#define BSZ  (32*BSTR)                  // 4352 floats
#define STG  (ASZ+BSZ)                  // 8960 floats / stage
#define MG_SMEM (3*STG*4)               // 107520 B; x2 CTA = 215KB <= 228KB

__device__ __forceinline__ uint32_t f2tf32(float f) {
    uint32_t u;
    asm("cvt.rna.tf32.f32 %0, %1;" : "=r"(u) : "f"(f));
    return u;
}
__device__ __forceinline__ uint32_t smem_u32(const void* p) {
    uint32_t a;
    asm("{ .reg .u64 t; cvta.to.shared.u64 t, %1; cvt.u32.u64 %0, t; }" : "=r"(a) : "l"(p));
    return a;
}
__device__ __forceinline__ void mma_tf32(float* d, const uint32_t* a, const uint32_t* b) {
    asm volatile(
        "mma.sync.aligned.m16n8k8.row.col.f32.tf32.tf32.f32 "
        "{%0,%1,%2,%3}, {%4,%5,%6,%7}, {%8,%9}, {%0,%1,%2,%3};"
        : "+f"(d[0]), "+f"(d[1]), "+f"(d[2]), "+f"(d[3])
        : "r"(a[0]), "r"(a[1]), "r"(a[2]), "r"(a[3]), "r"(b[0]), "r"(b[1]));
}
#define CP16(dst, src) \
    asm volatile("cp.async.cg.shared.global [%0], [%1], 16;" :: "r"(dst), "l"(src))
#define CP_COMMIT() asm volatile("cp.async.commit_group;" ::: "memory")
#define CP_WAIT1()  asm volatile("cp.async.wait_group 1;" ::: "memory")

__device__ __forceinline__ float silu_f(float x) {
    return x / (1.0f + __expf(-x));
}

template<int EPI>
__global__ __launch_bounds__(256, 2)
void mgemm_kernel(const float* __restrict__ A, const float* __restrict__ B,
                  float* __restrict__ C, int M, int N, int K, int ldc,
                  const float* __restrict__ bias, const float* __restrict__ res,
                  const float* __restrict__ mask, long sB, long sC)
{
    extern __shared__ __align__(16) float sm[];
    const uint32_t sb = smem_u32(sm);
    const int z = blockIdx.z;
    B += (long)z * sB;
    C += (long)z * sC;
    if (EPI >= 2) res += (long)z * sC;

    const int bm = blockIdx.y * 128, bn = blockIdx.x * 128;
    const int tid  = threadIdx.x;
    const int wid  = tid >> 5, lane = tid & 31;
    const int wm   = (wid & 1) * 64;
    const int wn   = (wid >> 1) * 32;
    const int gid  = lane >> 2;
    const int tig  = lane & 3;

    // cp.async stage load: A 1024 chunks (128 rows x 8), B 1024 chunks (32 rows x 32)
    const int ar = tid >> 3, akc = tid & 7;      // A: rows strided by 32
    const int br = tid >> 5, bc4 = tid & 31;     // B: rows strided by 8
    auto load_stage = [&](int t) {
        const int k0 = t * 32;
        const uint32_t base = sb + (uint32_t)((t % 3) * STG) * 4u;
        #pragma unroll
        for (int j = 0; j < 4; j++) {
            int row = ar + j*32;
            CP16(base + (uint32_t)(row*ASTR + akc*4)*4u,
                 A + (size_t)(bm + row) * K + k0 + akc*4);
        }
        #pragma unroll
        for (int j = 0; j < 4; j++) {
            int row = br + j*8;
            CP16(base + (uint32_t)(ASZ + row*BSTR + bc4*4)*4u,
                 B + (size_t)(k0 + row) * N + bn + bc4*4);
        }
    };

    float acc[4][4][4];
    #pragma unroll
    for (int mt = 0; mt < 4; mt++)
        #pragma unroll
        for (int nt = 0; nt < 4; nt++)
            acc[mt][nt][0]=acc[mt][nt][1]=acc[mt][nt][2]=acc[mt][nt][3]=0.0f;

    const int KT = K / 32;
    load_stage(0); CP_COMMIT();
    load_stage(1); CP_COMMIT();

    for (int t = 0; t < KT; t++) {
        CP_WAIT1();
        __syncthreads();
        if (t + 2 < KT) load_stage(t + 2);
        CP_COMMIT();

        const float* aS = sm + (t % 3) * STG;
        const float* bS = aS + ASZ;
        #pragma unroll
        for (int kk = 0; kk < 4; kk++) {
            const int kb = kk * 8;
            uint32_t af[4][4], bf[4][2];
            #pragma unroll
            for (int mt = 0; mt < 4; mt++) {
                const int m0 = wm + mt*16;
                af[mt][0] = f2tf32(aS[(m0+gid  )*ASTR + kb+tig  ]);
                af[mt][1] = f2tf32(aS[(m0+gid+8)*ASTR + kb+tig  ]);
                af[mt][2] = f2tf32(aS[(m0+gid  )*ASTR + kb+tig+4]);
                af[mt][3] = f2tf32(aS[(m0+gid+8)*ASTR + kb+tig+4]);
            }
            #pragma unroll
            for (int nt = 0; nt < 4; nt++) {
                const int n0 = wn + nt*8;
                bf[nt][0] = f2tf32(bS[(kb+tig  )*BSTR + n0+gid]);
                bf[nt][1] = f2tf32(bS[(kb+tig+4)*BSTR + n0+gid]);
            }
            #pragma unroll
            for (int mt = 0; mt < 4; mt++)
                #pragma unroll
                for (int nt = 0; nt < 4; nt++)
                    mma_tf32(acc[mt][nt], af[mt], bf[nt]);
        }
        __syncthreads();
    }

    // epilogue: rows = bm+wm+mt*16+gid(+8), cols = bn+wn+nt*8+2*tig(+1)
    #pragma unroll
    for (int mt = 0; mt < 4; mt++) {
        #pragma unroll
        for (int half = 0; half < 2; half++) {
            const int r = bm + wm + mt*16 + gid + half*8;
            float mrow = 0.0f;
            if (EPI == 4) mrow = mask[(size_t)r * NE + z];
            #pragma unroll
            for (int nt = 0; nt < 4; nt++) {
                const int c = bn + wn + nt*8 + tig*2;
                float2 o;
                o.x = acc[mt][nt][half*2 + 0];
                o.y = acc[mt][nt][half*2 + 1];
                if (EPI == 1) { o.x += bias[c]; o.y += bias[c+1]; }
                if (EPI == 2) {
                    float2 rv = *(const float2*)(res + (size_t)r * ldc + c);
                    o.x += rv.x; o.y += rv.y;
                }
                if (EPI == 3) {
                    float2 rv = *(const float2*)(res + (size_t)r * ldc + c);
                    o.x = silu_f(o.x) * rv.x;
                    o.y = silu_f(o.y) * rv.y;
                }
                if (EPI == 4) {
                    float2 rv = *(const float2*)(res + (size_t)r * ldc + c);
                    o.x = silu_f(o.x) * rv.x * mrow;
                    o.y = silu_f(o.y) * rv.y * mrow;
                }
                *(float2*)(C + (size_t)r * ldc + c) = o;
            }
        }
    }
}

// ---------------- RMSNorm ----------------
__global__ void rmsnorm_kernel(const float* __restrict__ x, const float* __restrict__ w,
                               float* __restrict__ out)
{
    int row = blockIdx.x;
    int tid = threadIdx.x;
    const float4 v = ((const float4*)(x + (size_t)row*DD))[tid];
    float ss = v.x*v.x + v.y*v.y + v.z*v.z + v.w*v.w;
    #pragma unroll
    for (int o = 16; o; o >>= 1) ss += __shfl_xor_sync(0xffffffffu, ss, o);
    __shared__ float red[8];
    if ((tid & 31) == 0) red[tid >> 5] = ss;
    __syncthreads();
    float total = red[0]+red[1]+red[2]+red[3]+red[4]+red[5]+red[6]+red[7];
    float sc = rsqrtf(total * (1.0f/DD) + 1e-6f);
    const float4 wv = ((const float4*)w)[tid];
    float4 o4;
    o4.x = v.x*sc*wv.x; o4.y = v.y*sc*wv.y; o4.z = v.z*sc*wv.z; o4.w = v.w*sc*wv.w;
    ((float4*)(out + (size_t)row*DD))[tid] = o4;
}

// ---------------- RoPE ----------------
__global__ void rope_kernel(float* __restrict__ buf, int nheads, long total)
{
    long idx = (long)blockIdx.x * blockDim.x + threadIdx.x;
    if (idx >= total) return;
    int  i    = (int)(idx & 31);
    int  head = (int)((idx >> 5) % nheads);
    long t    = idx / (32L * nheads);
    int  p    = (int)(t % PP);
    float inv = powf(10000.0f, -(float)i * (1.0f/32.0f));
    float ang = (float)p * inv;
    float c = cosf(ang), s = sinf(ang);
    float* v = buf + t * ((size_t)nheads * HDIM) + (size_t)head * HDIM + i;
    float a = v[0], b = v[32];
    v[0]  = a*c - b*s;
    v[32] = b*c + a*s;
}

// ---------------- causal flash attention (fp32) ----------------
__global__ __launch_bounds__(256, 2)
void flash_kernel(const float* __restrict__ q, const float* __restrict__ k,
                  const float* __restrict__ v, float* __restrict__ out)
{
    extern __shared__ float sm[];
    float* qs = sm;
    float* ks = sm + 64*68;
    float* vs = sm + 2*64*68;
    float* ps = sm + 3*64*68;

    const int b = blockIdx.z, h = blockIdx.y, qt = blockIdx.x;
    const int q0 = qt * 64;
    const float* qb = q + (size_t)b*PP*(HH*HDIM)  + (size_t)h*HDIM;
    const float* kb = k + (size_t)b*PP*(KVH*HDIM) + (size_t)(h>>1)*HDIM;
    const float* vb = v + (size_t)b*PP*(KVH*HDIM) + (size_t)(h>>1)*HDIM;

    const int tid = threadIdx.x;
    const int tx = tid & 15, ty = tid >> 4;
    const int lr = tid >> 4, lc = (tid & 15) * 4;

    for (int rr = lr; rr < 64; rr += 16) {
        float4 a = *(const float4*)(qb + (size_t)(q0+rr)*(HH*HDIM) + lc);
        qs[(lc+0)*68+rr] = a.x*0.125f; qs[(lc+1)*68+rr] = a.y*0.125f;
        qs[(lc+2)*68+rr] = a.z*0.125f; qs[(lc+3)*68+rr] = a.w*0.125f;
    }

    float m_i[4], l_i[4], o[4][4];
    #pragma unroll
    for (int i = 0; i < 4; i++) {
        m_i[i] = -1e30f; l_i[i] = 0.0f;
        o[i][0]=o[i][1]=o[i][2]=o[i][3]=0.0f;
    }

    for (int t = 0; t <= qt; t++) {
        const int k0 = t * 64;
        __syncthreads();
        for (int rr = lr; rr < 64; rr += 16) {
            float4 a = *(const float4*)(kb + (size_t)(k0+rr)*(KVH*HDIM) + lc);
            ks[(lc+0)*68+rr] = a.x; ks[(lc+1)*68+rr] = a.y;
            ks[(lc+2)*68+rr] = a.z; ks[(lc+3)*68+rr] = a.w;
            float4 w4 = *(const float4*)(vb + (size_t)(k0+rr)*(KVH*HDIM) + lc);
            *(float4*)(vs + rr*68 + lc) = w4;
        }
        __syncthreads();

        float s[4][4] = {{0,0,0,0},{0,0,0,0},{0,0,0,0},{0,0,0,0}};
        #pragma unroll 4
        for (int kk = 0; kk < 64; kk++) {
            float4 qa = *(const float4*)(qs + kk*68 + ty*4);
            float4 ka = *(const float4*)(ks + kk*68 + tx*4);
            float qr[4] = {qa.x,qa.y,qa.z,qa.w};
            float kr[4] = {ka.x,ka.y,ka.z,ka.w};
            #pragma unroll
            for (int i = 0; i < 4; i++)
                #pragma unroll
                for (int j = 0; j < 4; j++)
                    s[i][j] += qr[i]*kr[j];
        }

        if (t == qt) {
            #pragma unroll
            for (int i = 0; i < 4; i++)
                #pragma unroll
                for (int j = 0; j < 4; j++)
                    if (tx*4+j > ty*4+i) s[i][j] = -1e30f;
        }

        #pragma unroll
        for (int i = 0; i < 4; i++) {
            float rm = fmaxf(fmaxf(s[i][0],s[i][1]), fmaxf(s[i][2],s[i][3]));
            #pragma unroll
            for (int off = 8; off; off >>= 1)
                rm = fmaxf(rm, __shfl_xor_sync(0xffffffffu, rm, off));
            float nm = fmaxf(m_i[i], rm);
            float corr = __expf(m_i[i] - nm);
            m_i[i] = nm;
            float rs = 0.0f;
            #pragma unroll
            for (int j = 0; j < 4; j++) {
                float p = __expf(s[i][j] - nm);
                s[i][j] = p; rs += p;
            }
            #pragma unroll
            for (int off = 8; off; off >>= 1)
                rs += __shfl_xor_sync(0xffffffffu, rs, off);
            l_i[i] = l_i[i]*corr + rs;
            o[i][0]*=corr; o[i][1]*=corr; o[i][2]*=corr; o[i][3]*=corr;
        }

        #pragma unroll
        for (int i = 0; i < 4; i++)
            #pragma unroll
            for (int j = 0; j < 4; j++)
                ps[(tx*4+j)*68 + ty*4+i] = s[i][j];
        __syncthreads();

        #pragma unroll 4
        for (int kk = 0; kk < 64; kk++) {
            float4 pa = *(const float4*)(ps + kk*68 + ty*4);
            float4 va = *(const float4*)(vs + kk*68 + tx*4);
            float pr[4] = {pa.x,pa.y,pa.z,pa.w};
            float vr[4] = {va.x,va.y,va.z,va.w};
            #pragma unroll
            for (int i = 0; i < 4; i++)
                #pragma unroll
                for (int j = 0; j < 4; j++)
                    o[i][j] += pr[i]*vr[j];
        }
    }

    float* ob = out + (size_t)b*PP*DD + (size_t)h*HDIM;
    #pragma unroll
    for (int i = 0; i < 4; i++) {
        float inv = 1.0f / l_i[i];
        float4 r4;
        r4.x = o[i][0]*inv; r4.y = o[i][1]*inv; r4.z = o[i][2]*inv; r4.w = o[i][3]*inv;
        *(float4*)(ob + (size_t)(q0 + ty*4 + i)*DD + tx*4) = r4;
    }
}

// ---------------- launch ----------------
extern "C" void kernel_launch(void* const* d_in, const int* in_sizes, int n_in,
                              void* d_out, int out_size)
{
    const float* x        = (const float*)d_in[0];
    const float* emask    = (const float*)d_in[1];
    const float* ln1_w    = (const float*)d_in[2];
    const float* wq       = (const float*)d_in[3];
    const float* bq       = (const float*)d_in[4];
    const float* wk       = (const float*)d_in[5];
    const float* bk       = (const float*)d_in[6];
    const float* wv       = (const float*)d_in[7];
    const float* bv       = (const float*)d_in[8];
    const float* wo       = (const float*)d_in[9];
    const float* ln2_w    = (const float*)d_in[10];
    const float* w_gate   = (const float*)d_in[11];
    const float* w_up     = (const float*)d_in[12];
    const float* w_down   = (const float*)d_in[13];
    const float* we_gate  = (const float*)d_in[14];
    const float* we_up    = (const float*)d_in[15];
    const float* we_down  = (const float*)d_in[16];
    float* out = (float*)d_out;

    float *h,*q,*k,*v,*att,*x2,*h2,*gate,*up,*eg,*eu,*tmp;
    cudaGetSymbolAddress((void**)&h,   g_h);
    cudaGetSymbolAddress((void**)&q,   g_q);
    cudaGetSymbolAddress((void**)&k,   g_k);
    cudaGetSymbolAddress((void**)&v,   g_v);
    cudaGetSymbolAddress((void**)&att, g_att);
    cudaGetSymbolAddress((void**)&x2,  g_x2);
    cudaGetSymbolAddress((void**)&h2,  g_h2);
    cudaGetSymbolAddress((void**)&gate,g_gate);
    cudaGetSymbolAddress((void**)&up,  g_up);
    cudaGetSymbolAddress((void**)&eg,  g_eg);
    cudaGetSymbolAddress((void**)&eu,  g_eu);
    cudaGetSymbolAddress((void**)&tmp, g_tmp);

    cudaFuncSetAttribute(mgemm_kernel<0>, cudaFuncAttributeMaxDynamicSharedMemorySize, MG_SMEM);
    cudaFuncSetAttribute(mgemm_kernel<1>, cudaFuncAttributeMaxDynamicSharedMemorySize, MG_SMEM);
    cudaFuncSetAttribute(mgemm_kernel<2>, cudaFuncAttributeMaxDynamicSharedMemorySize, MG_SMEM);
    cudaFuncSetAttribute(mgemm_kernel<3>, cudaFuncAttributeMaxDynamicSharedMemorySize, MG_SMEM);
    cudaFuncSetAttribute(mgemm_kernel<4>, cudaFuncAttributeMaxDynamicSharedMemorySize, MG_SMEM);

    // 1) h = rmsnorm(x)
    rmsnorm_kernel<<<NTOK, 256>>>(x, ln1_w, h);

    // 2) QKV projections (+bias)
    mgemm_kernel<1><<<dim3(8,64,1), 256, MG_SMEM>>>(h, wq, q, NTOK, 1024, 1024, 1024, bq, nullptr, nullptr, 0, 0);
    mgemm_kernel<1><<<dim3(4,64,1), 256, MG_SMEM>>>(h, wk, k, NTOK,  512, 1024,  512, bk, nullptr, nullptr, 0, 0);
    mgemm_kernel<1><<<dim3(4,64,1), 256, MG_SMEM>>>(h, wv, v, NTOK,  512, 1024,  512, bv, nullptr, nullptr, 0, 0);

    // 3) RoPE
    {
        long tq = (long)NTOK * HH  * 32;
        rope_kernel<<<(unsigned)((tq + 255) / 256), 256>>>(q, HH, tq);
        long tk = (long)NTOK * KVH * 32;
        rope_kernel<<<(unsigned)((tk + 255) / 256), 256>>>(k, KVH, tk);
    }

    // 4) attention
    {
        int smem = 4 * 64 * 68 * (int)sizeof(float);
        cudaFuncSetAttribute(flash_kernel, cudaFuncAttributeMaxDynamicSharedMemorySize, smem);
        flash_kernel<<<dim3(PP/64, HH, BB), 256, smem>>>(q, k, v, att);
    }

    // 5) x2 = x + att @ wo
    mgemm_kernel<2><<<dim3(8,64,1), 256, MG_SMEM>>>(att, wo, x2, NTOK, 1024, 1024, 1024, nullptr, x, nullptr, 0, 0);

    // 6) h2 = rmsnorm(x2)
    rmsnorm_kernel<<<NTOK, 256>>>(x2, ln2_w, h2);

    // 7) dense MLP: up first, then gate with fused silu*up, then down(+res)
    mgemm_kernel<0><<<dim3(32,64,1), 256, MG_SMEM>>>(h2, w_up,   up,   NTOK, 4096, 1024, 4096, nullptr, nullptr, nullptr, 0, 0);
    mgemm_kernel<3><<<dim3(32,64,1), 256, MG_SMEM>>>(h2, w_gate, gate, NTOK, 4096, 1024, 4096, nullptr, up,      nullptr, 0, 0);
    mgemm_kernel<2><<<dim3(8,64,1),  256, MG_SMEM>>>(gate, w_down, tmp, NTOK, 1024, 4096, 1024, nullptr, x2,     nullptr, 0, 0);

    // 8) experts (z-batched): eu first, then eg with fused silu*eu*mask
    mgemm_kernel<0><<<dim3(2,64,NE), 256, MG_SMEM>>>(h2, we_up,   eu, NTOK, 256, 1024, 4096,
                                                     nullptr, nullptr, nullptr, (long)1024*256, 256);
    mgemm_kernel<4><<<dim3(2,64,NE), 256, MG_SMEM>>>(h2, we_gate, eg, NTOK, 256, 1024, 4096,
                                                     nullptr, eu, emask, (long)1024*256, 256);
    // 9) out = tmp + expert_acts @ we_down
    mgemm_kernel<2><<<dim3(8,64,1), 256, MG_SMEM>>>(eg, we_down, out, NTOK, 1024, 4096, 1024, nullptr, tmp, nullptr, 0, 0);
}

// round 12
// speedup vs baseline: 1.9299x; 1.9299x over previous
#include <cuda_runtime.h>
#include <cstdint>
#include <math.h>

// ---------------- problem constants ----------------
#define BB   4
#define PP   2048
#define DD   1024
#define HH   16
#define KVH  8
#define HDIM 64
#define FFN  4096
#define NE   16
#define FE   256
#define NTOK (BB*PP)          // 8192

// ---------------- scratch (no allocs allowed) ----------------
__device__ float g_h   [(size_t)NTOK*DD];
__device__ float g_q   [(size_t)NTOK*HH*HDIM];
__device__ float g_k   [(size_t)NTOK*KVH*HDIM];
__device__ float g_v   [(size_t)NTOK*KVH*HDIM];
__device__ float g_att [(size_t)NTOK*DD];
__device__ float g_x2  [(size_t)NTOK*DD];
__device__ float g_h2  [(size_t)NTOK*DD];
__device__ float g_gate[(size_t)NTOK*FFN];
__device__ float g_up  [(size_t)NTOK*FFN];
__device__ float g_eg  [(size_t)NTOK*NE*FE];
__device__ float g_eu  [(size_t)NTOK*NE*FE];
__device__ float g_tmp [(size_t)NTOK*DD];

// =================== common helpers ===================
__device__ __forceinline__ uint32_t f2tf32(float f) {
    uint32_t u;
    asm("cvt.rna.tf32.f32 %0, %1;" : "=r"(u) : "f"(f));
    return u;
}
__device__ __forceinline__ uint32_t smem_u32(const void* p) {
    uint32_t a;
    asm("{ .reg .u64 t; cvta.to.shared.u64 t, %1; cvt.u32.u64 %0, t; }" : "=r"(a) : "l"(p));
    return a;
}
__device__ __forceinline__ void mma_tf32(float* d, const uint32_t* a, const uint32_t* b) {
    asm volatile(
        "mma.sync.aligned.m16n8k8.row.col.f32.tf32.tf32.f32 "
        "{%0,%1,%2,%3}, {%4,%5,%6,%7}, {%8,%9}, {%0,%1,%2,%3};"
        : "+f"(d[0]), "+f"(d[1]), "+f"(d[2]), "+f"(d[3])
        : "r"(a[0]), "r"(a[1]), "r"(a[2]), "r"(a[3]), "r"(b[0]), "r"(b[1]));
}
#define CP16(dst, src) \
    asm volatile("cp.async.cg.shared.global [%0], [%1], 16;" :: "r"(dst), "l"(src))
#define CP_COMMIT() asm volatile("cp.async.commit_group;" ::: "memory")
#define CP_WAIT1()  asm volatile("cp.async.wait_group 1;" ::: "memory")

__device__ __forceinline__ float silu_f(float x) {
    return x / (1.0f + __expf(-x));
}
#define F2U __float_as_uint
#define U2F __uint_as_float

// =================== tf32 mma.sync GEMM, cp.async 3-stage (R10-validated) ===================
#define ASTR 36
#define BSTR 136
#define ASZ  (128*ASTR)
#define BSZ  (32*BSTR)
#define STG  (ASZ+BSZ)
#define MG_SMEM (3*STG*4)

template<int EPI>
__global__ __launch_bounds__(256, 2)
void mgemm_kernel(const float* __restrict__ A, const float* __restrict__ B,
                  float* __restrict__ C, int M, int N, int K, int ldc,
                  const float* __restrict__ bias, const float* __restrict__ res,
                  const float* __restrict__ mask, long sB, long sC)
{
    extern __shared__ __align__(16) float sm[];
    const uint32_t sb = smem_u32(sm);
    const int z = blockIdx.z;
    B += (long)z * sB;
    C += (long)z * sC;
    if (EPI >= 2) res += (long)z * sC;

    const int bm = blockIdx.y * 128, bn = blockIdx.x * 128;
    const int tid  = threadIdx.x;
    const int wid  = tid >> 5, lane = tid & 31;
    const int wm   = (wid & 1) * 64;
    const int wn   = (wid >> 1) * 32;
    const int gid  = lane >> 2;
    const int tig  = lane & 3;

    const int ar = tid >> 3, akc = tid & 7;
    const int br = tid >> 5, bc4 = tid & 31;
    auto load_stage = [&](int t) {
        const int k0 = t * 32;
        const uint32_t base = sb + (uint32_t)((t % 3) * STG) * 4u;
        #pragma unroll
        for (int j = 0; j < 4; j++) {
            int row = ar + j*32;
            CP16(base + (uint32_t)(row*ASTR + akc*4)*4u,
                 A + (size_t)(bm + row) * K + k0 + akc*4);
        }
        #pragma unroll
        for (int j = 0; j < 4; j++) {
            int row = br + j*8;
            CP16(base + (uint32_t)(ASZ + row*BSTR + bc4*4)*4u,
                 B + (size_t)(k0 + row) * N + bn + bc4*4);
        }
    };

    float acc[4][4][4];
    #pragma unroll
    for (int mt = 0; mt < 4; mt++)
        #pragma unroll
        for (int nt = 0; nt < 4; nt++)
            acc[mt][nt][0]=acc[mt][nt][1]=acc[mt][nt][2]=acc[mt][nt][3]=0.0f;

    const int KT = K / 32;
    load_stage(0); CP_COMMIT();
    load_stage(1); CP_COMMIT();

    for (int t = 0; t < KT; t++) {
        CP_WAIT1();
        __syncthreads();
        if (t + 2 < KT) load_stage(t + 2);
        CP_COMMIT();

        const float* aS = sm + (t % 3) * STG;
        const float* bS = aS + ASZ;
        #pragma unroll
        for (int kk = 0; kk < 4; kk++) {
            const int kb = kk * 8;
            uint32_t af[4][4], bf[4][2];
            #pragma unroll
            for (int mt = 0; mt < 4; mt++) {
                const int m0 = wm + mt*16;
                af[mt][0] = f2tf32(aS[(m0+gid  )*ASTR + kb+tig  ]);
                af[mt][1] = f2tf32(aS[(m0+gid+8)*ASTR + kb+tig  ]);
                af[mt][2] = f2tf32(aS[(m0+gid  )*ASTR + kb+tig+4]);
                af[mt][3] = f2tf32(aS[(m0+gid+8)*ASTR + kb+tig+4]);
            }
            #pragma unroll
            for (int nt = 0; nt < 4; nt++) {
                const int n0 = wn + nt*8;
                bf[nt][0] = f2tf32(bS[(kb+tig  )*BSTR + n0+gid]);
                bf[nt][1] = f2tf32(bS[(kb+tig+4)*BSTR + n0+gid]);
            }
            #pragma unroll
            for (int mt = 0; mt < 4; mt++)
                #pragma unroll
                for (int nt = 0; nt < 4; nt++)
                    mma_tf32(acc[mt][nt], af[mt], bf[nt]);
        }
        __syncthreads();
    }

    #pragma unroll
    for (int mt = 0; mt < 4; mt++) {
        #pragma unroll
        for (int half = 0; half < 2; half++) {
            const int r = bm + wm + mt*16 + gid + half*8;
            float mrow = 0.0f;
            if (EPI == 4) mrow = mask[(size_t)r * NE + z];
            #pragma unroll
            for (int nt = 0; nt < 4; nt++) {
                const int c = bn + wn + nt*8 + tig*2;
                float2 o;
                o.x = acc[mt][nt][half*2 + 0];
                o.y = acc[mt][nt][half*2 + 1];
                if (EPI == 1) { o.x += bias[c]; o.y += bias[c+1]; }
                if (EPI == 2) {
                    float2 rv = *(const float2*)(res + (size_t)r * ldc + c);
                    o.x += rv.x; o.y += rv.y;
                }
                if (EPI == 3) {
                    float2 rv = *(const float2*)(res + (size_t)r * ldc + c);
                    o.x = silu_f(o.x) * rv.x;
                    o.y = silu_f(o.y) * rv.y;
                }
                if (EPI == 4) {
                    float2 rv = *(const float2*)(res + (size_t)r * ldc + c);
                    o.x = silu_f(o.x) * rv.x * mrow;
                    o.y = silu_f(o.y) * rv.y * mrow;
                }
                *(float2*)(C + (size_t)r * ldc + c) = o;
            }
        }
    }
}

// ---------------- RMSNorm ----------------
__global__ void rmsnorm_kernel(const float* __restrict__ x, const float* __restrict__ w,
                               float* __restrict__ out)
{
    int row = blockIdx.x;
    int tid = threadIdx.x;
    const float4 v = ((const float4*)(x + (size_t)row*DD))[tid];
    float ss = v.x*v.x + v.y*v.y + v.z*v.z + v.w*v.w;
    #pragma unroll
    for (int o = 16; o; o >>= 1) ss += __shfl_xor_sync(0xffffffffu, ss, o);
    __shared__ float red[8];
    if ((tid & 31) == 0) red[tid >> 5] = ss;
    __syncthreads();
    float total = red[0]+red[1]+red[2]+red[3]+red[4]+red[5]+red[6]+red[7];
    float sc = rsqrtf(total * (1.0f/DD) + 1e-6f);
    const float4 wv = ((const float4*)w)[tid];
    float4 o4;
    o4.x = v.x*sc*wv.x; o4.y = v.y*sc*wv.y; o4.z = v.z*sc*wv.z; o4.w = v.w*sc*wv.w;
    ((float4*)(out + (size_t)row*DD))[tid] = o4;
}

// ---------------- RoPE ----------------
__global__ void rope_kernel(float* __restrict__ buf, int nheads, long total)
{
    long idx = (long)blockIdx.x * blockDim.x + threadIdx.x;
    if (idx >= total) return;
    int  i    = (int)(idx & 31);
    int  head = (int)((idx >> 5) % nheads);
    long t    = idx / (32L * nheads);
    int  p    = (int)(t % PP);
    float inv = powf(10000.0f, -(float)i * (1.0f/32.0f));
    float ang = (float)p * inv;
    float c = cosf(ang), s = sinf(ang);
    float* v = buf + t * ((size_t)nheads * HDIM) + (size_t)head * HDIM + i;
    float a = v[0], b = v[32];
    v[0]  = a*c - b*s;
    v[32] = b*c + a*s;
}

// ---------------- tf32 tensor-core causal flash attention ----------------
// CTA = 64 q-rows of one head; 4 warps, each warp a 16-row m-block (m16n64 S/O).
// Fragment conventions identical to mgemm (validated). Strides chosen so every
// fragment LDS is bank-conflict-free: Q/K/P stride 68 (bank=4*gid+tig),
// V stride 72 (bank=8*tig+gid).
#define FSTR 68
#define VSTR 72
#define FL_SMEM ((3*64*FSTR + 64*VSTR)*4)   // qs+ks+ps + vs = 70656 B

__global__ __launch_bounds__(128, 3)
void flash_tc_kernel(const float* __restrict__ q, const float* __restrict__ k,
                     const float* __restrict__ v, float* __restrict__ out)
{
    extern __shared__ float sm[];
    float* qs = sm;                 // [64][FSTR] q rows (tf32 bits, pre-scaled)
    float* ks = sm + 64*FSTR;       // [64][FSTR] k rows
    float* ps = sm + 2*64*FSTR;     // [64][FSTR] P (warp-private 16-row slices)
    float* vs = sm + 3*64*FSTR;     // [64][VSTR] v rows

    const int b = blockIdx.z, h = blockIdx.y, qt = blockIdx.x;
    const int q0 = qt * 64;
    const float* qb = q + (size_t)b*PP*(HH*HDIM)  + (size_t)h*HDIM;
    const float* kb = k + (size_t)b*PP*(KVH*HDIM) + (size_t)(h>>1)*HDIM;
    const float* vb = v + (size_t)b*PP*(KVH*HDIM) + (size_t)(h>>1)*HDIM;

    const int tid = threadIdx.x;
    const int wid = tid >> 5, lane = tid & 31;
    const int gid = lane >> 2, tig = lane & 3;
    const int m0  = wid * 16;

    // load Q tile (scale by 1/sqrt(64)=0.125, convert to tf32)
    #pragma unroll
    for (int i = 0; i < 8; i++) {
        int idx = tid + i*128;
        int row = idx >> 4, c4 = (idx & 15) * 4;
        float4 a = *(const float4*)(qb + (size_t)(q0+row)*(HH*HDIM) + c4);
        qs[row*FSTR + c4+0] = U2F(f2tf32(a.x*0.125f));
        qs[row*FSTR + c4+1] = U2F(f2tf32(a.y*0.125f));
        qs[row*FSTR + c4+2] = U2F(f2tf32(a.z*0.125f));
        qs[row*FSTR + c4+3] = U2F(f2tf32(a.w*0.125f));
    }

    float m_i[2] = {-1e30f, -1e30f};
    float l_i[2] = {0.0f, 0.0f};
    float o[8][4];
    #pragma unroll
    for (int j = 0; j < 8; j++) o[j][0]=o[j][1]=o[j][2]=o[j][3]=0.0f;

    for (int t = 0; t <= qt; t++) {
        const int k0 = t * 64;
        __syncthreads();
        // load K and V tiles (tf32)
        #pragma unroll
        for (int i = 0; i < 8; i++) {
            int idx = tid + i*128;
            int row = idx >> 4, c4 = (idx & 15) * 4;
            float4 a = *(const float4*)(kb + (size_t)(k0+row)*(KVH*HDIM) + c4);
            ks[row*FSTR + c4+0] = U2F(f2tf32(a.x));
            ks[row*FSTR + c4+1] = U2F(f2tf32(a.y));
            ks[row*FSTR + c4+2] = U2F(f2tf32(a.z));
            ks[row*FSTR + c4+3] = U2F(f2tf32(a.w));
            float4 w4 = *(const float4*)(vb + (size_t)(k0+row)*(KVH*HDIM) + c4);
            vs[row*VSTR + c4+0] = U2F(f2tf32(w4.x));
            vs[row*VSTR + c4+1] = U2F(f2tf32(w4.y));
            vs[row*VSTR + c4+2] = U2F(f2tf32(w4.z));
            vs[row*VSTR + c4+3] = U2F(f2tf32(w4.w));
        }
        __syncthreads();

        // S = Q @ K^T   (m16 x n64 per warp)
        float sacc[8][4];
        #pragma unroll
        for (int j = 0; j < 8; j++) sacc[j][0]=sacc[j][1]=sacc[j][2]=sacc[j][3]=0.0f;
        #pragma unroll
        for (int kc = 0; kc < 8; kc++) {
            const int kb8 = kc * 8;
            uint32_t av[4];
            av[0] = F2U(qs[(m0+gid  )*FSTR + kb8+tig  ]);
            av[1] = F2U(qs[(m0+gid+8)*FSTR + kb8+tig  ]);
            av[2] = F2U(qs[(m0+gid  )*FSTR + kb8+tig+4]);
            av[3] = F2U(qs[(m0+gid+8)*FSTR + kb8+tig+4]);
            #pragma unroll
            for (int j = 0; j < 8; j++) {
                uint32_t bv[2];
                bv[0] = F2U(ks[(j*8+gid)*FSTR + kb8+tig  ]);
                bv[1] = F2U(ks[(j*8+gid)*FSTR + kb8+tig+4]);
                mma_tf32(sacc[j], av, bv);
            }
        }

        // causal mask on the diagonal tile
        if (t == qt) {
            #pragma unroll
            for (int j = 0; j < 8; j++)
                #pragma unroll
                for (int e = 0; e < 4; e++) {
                    int row = q0 + m0 + gid + ((e >> 1) << 3);
                    int col = k0 + j*8 + tig*2 + (e & 1);
                    if (col > row) sacc[j][e] = -1e30f;
                }
        }

        // online softmax: rows gid (r=0) and gid+8 (r=1); each row lives in a 4-lane quad
        #pragma unroll
        for (int r = 0; r < 2; r++) {
            float rm = -1e30f;
            #pragma unroll
            for (int j = 0; j < 8; j++)
                rm = fmaxf(rm, fmaxf(sacc[j][r*2], sacc[j][r*2+1]));
            rm = fmaxf(rm, __shfl_xor_sync(0xffffffffu, rm, 1));
            rm = fmaxf(rm, __shfl_xor_sync(0xffffffffu, rm, 2));
            float nm = fmaxf(m_i[r], rm);
            float corr = __expf(m_i[r] - nm);
            m_i[r] = nm;
            float rs = 0.0f;
            #pragma unroll
            for (int j = 0; j < 8; j++) {
                float p0 = __expf(sacc[j][r*2  ] - nm);
                float p1 = __expf(sacc[j][r*2+1] - nm);
                sacc[j][r*2] = p0; sacc[j][r*2+1] = p1;
                rs += p0 + p1;
            }
            rs += __shfl_xor_sync(0xffffffffu, rs, 1);
            rs += __shfl_xor_sync(0xffffffffu, rs, 2);
            l_i[r] = l_i[r]*corr + rs;
            #pragma unroll
            for (int j = 0; j < 8; j++) { o[j][r*2] *= corr; o[j][r*2+1] *= corr; }
        }

        // store P (tf32) to warp-private smem slice
        #pragma unroll
        for (int j = 0; j < 8; j++) {
            ps[(m0+gid  )*FSTR + j*8 + tig*2    ] = U2F(f2tf32(sacc[j][0]));
            ps[(m0+gid  )*FSTR + j*8 + tig*2 + 1] = U2F(f2tf32(sacc[j][1]));
            ps[(m0+gid+8)*FSTR + j*8 + tig*2    ] = U2F(f2tf32(sacc[j][2]));
            ps[(m0+gid+8)*FSTR + j*8 + tig*2 + 1] = U2F(f2tf32(sacc[j][3]));
        }
        __syncwarp();

        // O += P @ V
        #pragma unroll
        for (int kc = 0; kc < 8; kc++) {
            const int kb8 = kc * 8;
            uint32_t av[4];
            av[0] = F2U(ps[(m0+gid  )*FSTR + kb8+tig  ]);
            av[1] = F2U(ps[(m0+gid+8)*FSTR + kb8+tig  ]);
            av[2] = F2U(ps[(m0+gid  )*FSTR + kb8+tig+4]);
            av[3] = F2U(ps[(m0+gid+8)*FSTR + kb8+tig+4]);
            #pragma unroll
            for (int j = 0; j < 8; j++) {
                uint32_t bv[2];
                bv[0] = F2U(vs[(kb8+tig  )*VSTR + j*8+gid]);
                bv[1] = F2U(vs[(kb8+tig+4)*VSTR + j*8+gid]);
                mma_tf32(o[j], av, bv);
            }
        }
    }

    const float inv0 = 1.0f / l_i[0];
    const float inv1 = 1.0f / l_i[1];
    float* ob = out + (size_t)b*PP*DD + (size_t)h*HDIM;
    #pragma unroll
    for (int j = 0; j < 8; j++) {
        int c = j*8 + tig*2;
        *(float2*)(ob + (size_t)(q0+m0+gid  )*DD + c) = make_float2(o[j][0]*inv0, o[j][1]*inv0);
        *(float2*)(ob + (size_t)(q0+m0+gid+8)*DD + c) = make_float2(o[j][2]*inv1, o[j][3]*inv1);
    }
}

// ---------------- launch ----------------
extern "C" void kernel_launch(void* const* d_in, const int* in_sizes, int n_in,
                              void* d_out, int out_size)
{
    const float* x        = (const float*)d_in[0];
    const float* emask    = (const float*)d_in[1];
    const float* ln1_w    = (const float*)d_in[2];
    const float* wq       = (const float*)d_in[3];
    const float* bq       = (const float*)d_in[4];
    const float* wk       = (const float*)d_in[5];
    const float* bk       = (const float*)d_in[6];
    const float* wv       = (const float*)d_in[7];
    const float* bv       = (const float*)d_in[8];
    const float* wo       = (const float*)d_in[9];
    const float* ln2_w    = (const float*)d_in[10];
    const float* w_gate   = (const float*)d_in[11];
    const float* w_up     = (const float*)d_in[12];
    const float* w_down   = (const float*)d_in[13];
    const float* we_gate  = (const float*)d_in[14];
    const float* we_up    = (const float*)d_in[15];
    const float* we_down  = (const float*)d_in[16];
    float* out = (float*)d_out;

    float *h,*q,*k,*v,*att,*x2,*h2,*gate,*up,*eg,*eu,*tmp;
    cudaGetSymbolAddress((void**)&h,   g_h);
    cudaGetSymbolAddress((void**)&q,   g_q);
    cudaGetSymbolAddress((void**)&k,   g_k);
    cudaGetSymbolAddress((void**)&v,   g_v);
    cudaGetSymbolAddress((void**)&att, g_att);
    cudaGetSymbolAddress((void**)&x2,  g_x2);
    cudaGetSymbolAddress((void**)&h2,  g_h2);
    cudaGetSymbolAddress((void**)&gate,g_gate);
    cudaGetSymbolAddress((void**)&up,  g_up);
    cudaGetSymbolAddress((void**)&eg,  g_eg);
    cudaGetSymbolAddress((void**)&eu,  g_eu);
    cudaGetSymbolAddress((void**)&tmp, g_tmp);

    cudaFuncSetAttribute(mgemm_kernel<0>, cudaFuncAttributeMaxDynamicSharedMemorySize, MG_SMEM);
    cudaFuncSetAttribute(mgemm_kernel<1>, cudaFuncAttributeMaxDynamicSharedMemorySize, MG_SMEM);
    cudaFuncSetAttribute(mgemm_kernel<2>, cudaFuncAttributeMaxDynamicSharedMemorySize, MG_SMEM);
    cudaFuncSetAttribute(mgemm_kernel<3>, cudaFuncAttributeMaxDynamicSharedMemorySize, MG_SMEM);
    cudaFuncSetAttribute(mgemm_kernel<4>, cudaFuncAttributeMaxDynamicSharedMemorySize, MG_SMEM);
    cudaFuncSetAttribute(flash_tc_kernel, cudaFuncAttributeMaxDynamicSharedMemorySize, FL_SMEM);

    // 1) h = rmsnorm(x)
    rmsnorm_kernel<<<NTOK, 256>>>(x, ln1_w, h);

    // 2) QKV projections (+bias)
    mgemm_kernel<1><<<dim3(8,64,1), 256, MG_SMEM>>>(h, wq, q, NTOK, 1024, 1024, 1024, bq, nullptr, nullptr, 0, 0);
    mgemm_kernel<1><<<dim3(4,64,1), 256, MG_SMEM>>>(h, wk, k, NTOK,  512, 1024,  512, bk, nullptr, nullptr, 0, 0);
    mgemm_kernel<1><<<dim3(4,64,1), 256, MG_SMEM>>>(h, wv, v, NTOK,  512, 1024,  512, bv, nullptr, nullptr, 0, 0);

    // 3) RoPE
    {
        long tq = (long)NTOK * HH  * 32;
        rope_kernel<<<(unsigned)((tq + 255) / 256), 256>>>(q, HH, tq);
        long tk = (long)NTOK * KVH * 32;
        rope_kernel<<<(unsigned)((tk + 255) / 256), 256>>>(k, KVH, tk);
    }

    // 4) attention (tf32 tensor cores)
    flash_tc_kernel<<<dim3(PP/64, HH, BB), 128, FL_SMEM>>>(q, k, v, att);

    // 5) x2 = x + att @ wo
    mgemm_kernel<2><<<dim3(8,64,1), 256, MG_SMEM>>>(att, wo, x2, NTOK, 1024, 1024, 1024, nullptr, x, nullptr, 0, 0);

    // 6) h2 = rmsnorm(x2)
    rmsnorm_kernel<<<NTOK, 256>>>(x2, ln2_w, h2);

    // 7) dense MLP: up first, then gate with fused silu*up, then down(+res)
    mgemm_kernel<0><<<dim3(32,64,1), 256, MG_SMEM>>>(h2, w_up,   up,   NTOK, 4096, 1024, 4096, nullptr, nullptr, nullptr, 0, 0);
    mgemm_kernel<3><<<dim3(32,64,1), 256, MG_SMEM>>>(h2, w_gate, gate, NTOK, 4096, 1024, 4096, nullptr, up,      nullptr, 0, 0);
    mgemm_kernel<2><<<dim3(8,64,1),  256, MG_SMEM>>>(gate, w_down, tmp, NTOK, 1024, 4096, 1024, nullptr, x2,     nullptr, 0, 0);

    // 8) experts (z-batched): eu first, then eg with fused silu*eu*mask
    mgemm_kernel<0><<<dim3(2,64,NE), 256, MG_SMEM>>>(h2, we_up,   eu, NTOK, 256, 1024, 4096,
                                                     nullptr, nullptr, nullptr, (long)1024*256, 256);
    mgemm_kernel<4><<<dim3(2,64,NE), 256, MG_SMEM>>>(h2, we_gate, eg, NTOK, 256, 1024, 4096,
                                                     nullptr, eu, emask, (long)1024*256, 256);
    // 9) out = tmp + expert_acts @ we_down
    mgemm_kernel<2><<<dim3(8,64,1), 256, MG_SMEM>>>(eg, we_down, out, NTOK, 1024, 4096, 1024, nullptr, tmp, nullptr, 0, 0);
}

// round 14
// speedup vs baseline: 2.1263x; 1.1018x over previous
#include <cuda_runtime.h>
#include <cstdint>
#include <math.h>

// ---------------- problem constants ----------------
#define BB   4
#define PP   2048
#define DD   1024
#define HH   16
#define KVH  8
#define HDIM 64
#define FFN  4096
#define NE   16
#define FE   256
#define NTOK (BB*PP)          // 8192

// ---------------- scratch (no allocs allowed) ----------------
__device__ float g_h   [(size_t)NTOK*DD];
__device__ float g_q   [(size_t)NTOK*HH*HDIM];
__device__ float g_k   [(size_t)NTOK*KVH*HDIM];
__device__ float g_v   [(size_t)NTOK*KVH*HDIM];
__device__ float g_att [(size_t)NTOK*DD];
__device__ float g_x2  [(size_t)NTOK*DD];
__device__ float g_h2  [(size_t)NTOK*DD];
__device__ float g_gate[(size_t)NTOK*FFN];
__device__ float g_up  [(size_t)NTOK*FFN];
__device__ float g_eg  [(size_t)NTOK*NE*FE];
__device__ float g_eu  [(size_t)NTOK*NE*FE];
__device__ float g_tmp [(size_t)NTOK*DD];

// =================== common helpers ===================
// NOTE: tf32 HMMA reads only the upper 19 bits of each operand register, so
// feeding raw fp32 bits == RZ truncation to tf32 with ZERO cvt instructions.
__device__ __forceinline__ uint32_t smem_u32(const void* p) {
    uint32_t a;
    asm("{ .reg .u64 t; cvta.to.shared.u64 t, %1; cvt.u32.u64 %0, t; }" : "=r"(a) : "l"(p));
    return a;
}
__device__ __forceinline__ void mma_tf32(float* d, const uint32_t* a, const uint32_t* b) {
    asm volatile(
        "mma.sync.aligned.m16n8k8.row.col.f32.tf32.tf32.f32 "
        "{%0,%1,%2,%3}, {%4,%5,%6,%7}, {%8,%9}, {%0,%1,%2,%3};"
        : "+f"(d[0]), "+f"(d[1]), "+f"(d[2]), "+f"(d[3])
        : "r"(a[0]), "r"(a[1]), "r"(a[2]), "r"(a[3]), "r"(b[0]), "r"(b[1]));
}
#define CP16(dst, src) \
    asm volatile("cp.async.cg.shared.global [%0], [%1], 16;" :: "r"(dst), "l"(src))
#define CP_COMMIT() asm volatile("cp.async.commit_group;" ::: "memory")
#define CP_WAIT1()  asm volatile("cp.async.wait_group 1;" ::: "memory")

__device__ __forceinline__ float silu_f(float x) {
    return x / (1.0f + __expf(-x));
}
#define F2U __float_as_uint
#define U2F __uint_as_float

// =================== tf32 mma.sync GEMM, cp.async 3-stage ===================
#define ASTR 36
#define BSTR 136
#define ASZ  (128*ASTR)
#define BSZ  (32*BSTR)
#define STG  (ASZ+BSZ)
#define MG_SMEM (3*STG*4)

template<int EPI>
__global__ __launch_bounds__(256, 2)
void mgemm_kernel(const float* __restrict__ A, const float* __restrict__ B,
                  float* __restrict__ C, int M, int N, int K, int ldc,
                  const float* __restrict__ bias, const float* __restrict__ res,
                  const float* __restrict__ mask, long sB, long sC)
{
    extern __shared__ __align__(16) float sm[];
    const uint32_t sb = smem_u32(sm);
    const int z = blockIdx.z;
    B += (long)z * sB;
    C += (long)z * sC;
    if (EPI >= 2) res += (long)z * sC;

    const int bm = blockIdx.y * 128, bn = blockIdx.x * 128;
    const int tid  = threadIdx.x;
    const int wid  = tid >> 5, lane = tid & 31;
    const int wm   = (wid & 1) * 64;
    const int wn   = (wid >> 1) * 32;
    const int gid  = lane >> 2;
    const int tig  = lane & 3;

    const int ar = tid >> 3, akc = tid & 7;
    const int br = tid >> 5, bc4 = tid & 31;
    auto load_stage = [&](int t) {
        const int k0 = t * 32;
        const uint32_t base = sb + (uint32_t)((t % 3) * STG) * 4u;
        #pragma unroll
        for (int j = 0; j < 4; j++) {
            int row = ar + j*32;
            CP16(base + (uint32_t)(row*ASTR + akc*4)*4u,
                 A + (size_t)(bm + row) * K + k0 + akc*4);
        }
        #pragma unroll
        for (int j = 0; j < 4; j++) {
            int row = br + j*8;
            CP16(base + (uint32_t)(ASZ + row*BSTR + bc4*4)*4u,
                 B + (size_t)(k0 + row) * N + bn + bc4*4);
        }
    };

    float acc[4][4][4];
    #pragma unroll
    for (int mt = 0; mt < 4; mt++)
        #pragma unroll
        for (int nt = 0; nt < 4; nt++)
            acc[mt][nt][0]=acc[mt][nt][1]=acc[mt][nt][2]=acc[mt][nt][3]=0.0f;

    const int KT = K / 32;
    load_stage(0); CP_COMMIT();
    load_stage(1); CP_COMMIT();

    for (int t = 0; t < KT; t++) {
        CP_WAIT1();
        __syncthreads();
        if (t + 2 < KT) load_stage(t + 2);
        CP_COMMIT();

        const float* aS = sm + (t % 3) * STG;
        const float* bS = aS + ASZ;
        #pragma unroll
        for (int kk = 0; kk < 4; kk++) {
            const int kb = kk * 8;
            uint32_t af[4][4], bf[4][2];
            #pragma unroll
            for (int mt = 0; mt < 4; mt++) {
                const int m0 = wm + mt*16;
                af[mt][0] = F2U(aS[(m0+gid  )*ASTR + kb+tig  ]);
                af[mt][1] = F2U(aS[(m0+gid+8)*ASTR + kb+tig  ]);
                af[mt][2] = F2U(aS[(m0+gid  )*ASTR + kb+tig+4]);
                af[mt][3] = F2U(aS[(m0+gid+8)*ASTR + kb+tig+4]);
            }
            #pragma unroll
            for (int nt = 0; nt < 4; nt++) {
                const int n0 = wn + nt*8;
                bf[nt][0] = F2U(bS[(kb+tig  )*BSTR + n0+gid]);
                bf[nt][1] = F2U(bS[(kb+tig+4)*BSTR + n0+gid]);
            }
            #pragma unroll
            for (int mt = 0; mt < 4; mt++)
                #pragma unroll
                for (int nt = 0; nt < 4; nt++)
                    mma_tf32(acc[mt][nt], af[mt], bf[nt]);
        }
        __syncthreads();
    }

    #pragma unroll
    for (int mt = 0; mt < 4; mt++) {
        #pragma unroll
        for (int half = 0; half < 2; half++) {
            const int r = bm + wm + mt*16 + gid + half*8;
            float mrow = 0.0f;
            if (EPI == 4) mrow = mask[(size_t)r * NE + z];
            #pragma unroll
            for (int nt = 0; nt < 4; nt++) {
                const int c = bn + wn + nt*8 + tig*2;
                float2 o;
                o.x = acc[mt][nt][half*2 + 0];
                o.y = acc[mt][nt][half*2 + 1];
                if (EPI == 1) { o.x += bias[c]; o.y += bias[c+1]; }
                if (EPI == 2) {
                    float2 rv = *(const float2*)(res + (size_t)r * ldc + c);
                    o.x += rv.x; o.y += rv.y;
                }
                if (EPI == 3) {
                    float2 rv = *(const float2*)(res + (size_t)r * ldc + c);
                    o.x = silu_f(o.x) * rv.x;
                    o.y = silu_f(o.y) * rv.y;
                }
                if (EPI == 4) {
                    float2 rv = *(const float2*)(res + (size_t)r * ldc + c);
                    o.x = silu_f(o.x) * rv.x * mrow;
                    o.y = silu_f(o.y) * rv.y * mrow;
                }
                *(float2*)(C + (size_t)r * ldc + c) = o;
            }
        }
    }
}

// ---------------- RMSNorm ----------------
__global__ void rmsnorm_kernel(const float* __restrict__ x, const float* __restrict__ w,
                               float* __restrict__ out)
{
    int row = blockIdx.x;
    int tid = threadIdx.x;
    const float4 v = ((const float4*)(x + (size_t)row*DD))[tid];
    float ss = v.x*v.x + v.y*v.y + v.z*v.z + v.w*v.w;
    #pragma unroll
    for (int o = 16; o; o >>= 1) ss += __shfl_xor_sync(0xffffffffu, ss, o);
    __shared__ float red[8];
    if ((tid & 31) == 0) red[tid >> 5] = ss;
    __syncthreads();
    float total = red[0]+red[1]+red[2]+red[3]+red[4]+red[5]+red[6]+red[7];
    float sc = rsqrtf(total * (1.0f/DD) + 1e-6f);
    const float4 wv = ((const float4*)w)[tid];
    float4 o4;
    o4.x = v.x*sc*wv.x; o4.y = v.y*sc*wv.y; o4.z = v.z*sc*wv.z; o4.w = v.w*sc*wv.w;
    ((float4*)(out + (size_t)row*DD))[tid] = o4;
}

// ---------------- RoPE ----------------
__global__ void rope_kernel(float* __restrict__ buf, int nheads, long total)
{
    long idx = (long)blockIdx.x * blockDim.x + threadIdx.x;
    if (idx >= total) return;
    int  i    = (int)(idx & 31);
    int  head = (int)((idx >> 5) % nheads);
    long t    = idx / (32L * nheads);
    int  p    = (int)(t % PP);
    float inv = powf(10000.0f, -(float)i * (1.0f/32.0f));
    float ang = (float)p * inv;
    float c = cosf(ang), s = sinf(ang);
    float* v = buf + t * ((size_t)nheads * HDIM) + (size_t)head * HDIM + i;
    float a = v[0], b = v[32];
    v[0]  = a*c - b*s;
    v[32] = b*c + a*s;
}

// ---------------- tf32 tensor-core causal flash attention ----------------
#define FSTR 68
#define VSTR 72
#define FL_SMEM ((3*64*FSTR + 64*VSTR)*4)   // 70656 B

__global__ __launch_bounds__(128, 3)
void flash_tc_kernel(const float* __restrict__ q, const float* __restrict__ k,
                     const float* __restrict__ v, float* __restrict__ out)
{
    extern __shared__ float sm[];
    float* qs = sm;                 // [64][FSTR]
    float* ks = sm + 64*FSTR;       // [64][FSTR]
    float* ps = sm + 2*64*FSTR;     // [64][FSTR]
    float* vs = sm + 3*64*FSTR;     // [64][VSTR]

    const int b = blockIdx.z, h = blockIdx.y, qt = blockIdx.x;
    const int q0 = qt * 64;
    const float* qb = q + (size_t)b*PP*(HH*HDIM)  + (size_t)h*HDIM;
    const float* kb = k + (size_t)b*PP*(KVH*HDIM) + (size_t)(h>>1)*HDIM;
    const float* vb = v + (size_t)b*PP*(KVH*HDIM) + (size_t)(h>>1)*HDIM;

    const int tid = threadIdx.x;
    const int wid = tid >> 5, lane = tid & 31;
    const int gid = lane >> 2, tig = lane & 3;
    const int m0  = wid * 16;

    // load Q tile (scale by 1/sqrt(64)=0.125); raw fp32 bits (HMMA truncates)
    #pragma unroll
    for (int i = 0; i < 8; i++) {
        int idx = tid + i*128;
        int row = idx >> 4, c4 = (idx & 15) * 4;
        float4 a = *(const float4*)(qb + (size_t)(q0+row)*(HH*HDIM) + c4);
        a.x *= 0.125f; a.y *= 0.125f; a.z *= 0.125f; a.w *= 0.125f;
        *(float4*)(qs + row*FSTR + c4) = a;
    }

    float m_i[2] = {-1e30f, -1e30f};
    float l_i[2] = {0.0f, 0.0f};
    float o[8][4];
    #pragma unroll
    for (int j = 0; j < 8; j++) o[j][0]=o[j][1]=o[j][2]=o[j][3]=0.0f;

    for (int t = 0; t <= qt; t++) {
        const int k0 = t * 64;
        __syncthreads();
        #pragma unroll
        for (int i = 0; i < 8; i++) {
            int idx = tid + i*128;
            int row = idx >> 4, c4 = (idx & 15) * 4;
            *(float4*)(ks + row*FSTR + c4) =
                *(const float4*)(kb + (size_t)(k0+row)*(KVH*HDIM) + c4);
            *(float4*)(vs + row*VSTR + c4) =
                *(const float4*)(vb + (size_t)(k0+row)*(KVH*HDIM) + c4);
        }
        __syncthreads();

        // S = Q @ K^T   (m16 x n64 per warp)
        float sacc[8][4];
        #pragma unroll
        for (int j = 0; j < 8; j++) sacc[j][0]=sacc[j][1]=sacc[j][2]=sacc[j][3]=0.0f;
        #pragma unroll
        for (int kc = 0; kc < 8; kc++) {
            const int kb8 = kc * 8;
            uint32_t av[4];
            av[0] = F2U(qs[(m0+gid  )*FSTR + kb8+tig  ]);
            av[1] = F2U(qs[(m0+gid+8)*FSTR + kb8+tig  ]);
            av[2] = F2U(qs[(m0+gid  )*FSTR + kb8+tig+4]);
            av[3] = F2U(qs[(m0+gid+8)*FSTR + kb8+tig+4]);
            #pragma unroll
            for (int j = 0; j < 8; j++) {
                uint32_t bv[2];
                bv[0] = F2U(ks[(j*8+gid)*FSTR + kb8+tig  ]);
                bv[1] = F2U(ks[(j*8+gid)*FSTR + kb8+tig+4]);
                mma_tf32(sacc[j], av, bv);
            }
        }

        if (t == qt) {
            #pragma unroll
            for (int j = 0; j < 8; j++)
                #pragma unroll
                for (int e = 0; e < 4; e++) {
                    int row = q0 + m0 + gid + ((e >> 1) << 3);
                    int col = k0 + j*8 + tig*2 + (e & 1);
                    if (col > row) sacc[j][e] = -1e30f;
                }
        }

        #pragma unroll
        for (int r = 0; r < 2; r++) {
            float rm = -1e30f;
            #pragma unroll
            for (int j = 0; j < 8; j++)
                rm = fmaxf(rm, fmaxf(sacc[j][r*2], sacc[j][r*2+1]));
            rm = fmaxf(rm, __shfl_xor_sync(0xffffffffu, rm, 1));
            rm = fmaxf(rm, __shfl_xor_sync(0xffffffffu, rm, 2));
            float nm = fmaxf(m_i[r], rm);
            float corr = __expf(m_i[r] - nm);
            m_i[r] = nm;
            float rs = 0.0f;
            #pragma unroll
            for (int j = 0; j < 8; j++) {
                float p0 = __expf(sacc[j][r*2  ] - nm);
                float p1 = __expf(sacc[j][r*2+1] - nm);
                sacc[j][r*2] = p0; sacc[j][r*2+1] = p1;
                rs += p0 + p1;
            }
            rs += __shfl_xor_sync(0xffffffffu, rs, 1);
            rs += __shfl_xor_sync(0xffffffffu, rs, 2);
            l_i[r] = l_i[r]*corr + rs;
            #pragma unroll
            for (int j = 0; j < 8; j++) { o[j][r*2] *= corr; o[j][r*2+1] *= corr; }
        }

        // store P (raw fp32 bits) to warp-private smem slice
        #pragma unroll
        for (int j = 0; j < 8; j++) {
            *(float2*)(ps + (m0+gid  )*FSTR + j*8 + tig*2) = make_float2(sacc[j][0], sacc[j][1]);
            *(float2*)(ps + (m0+gid+8)*FSTR + j*8 + tig*2) = make_float2(sacc[j][2], sacc[j][3]);
        }
        __syncwarp();

        // O += P @ V
        #pragma unroll
        for (int kc = 0; kc < 8; kc++) {
            const int kb8 = kc * 8;
            uint32_t av[4];
            av[0] = F2U(ps[(m0+gid  )*FSTR + kb8+tig  ]);
            av[1] = F2U(ps[(m0+gid+8)*FSTR + kb8+tig  ]);
            av[2] = F2U(ps[(m0+gid  )*FSTR + kb8+tig+4]);
            av[3] = F2U(ps[(m0+gid+8)*FSTR + kb8+tig+4]);
            #pragma unroll
            for (int j = 0; j < 8; j++) {
                uint32_t bv[2];
                bv[0] = F2U(vs[(kb8+tig  )*VSTR + j*8+gid]);
                bv[1] = F2U(vs[(kb8+tig+4)*VSTR + j*8+gid]);
                mma_tf32(o[j], av, bv);
            }
        }
    }

    const float inv0 = 1.0f / l_i[0];
    const float inv1 = 1.0f / l_i[1];
    float* ob = out + (size_t)b*PP*DD + (size_t)h*HDIM;
    #pragma unroll
    for (int j = 0; j < 8; j++) {
        int c = j*8 + tig*2;
        *(float2*)(ob + (size_t)(q0+m0+gid  )*DD + c) = make_float2(o[j][0]*inv0, o[j][1]*inv0);
        *(float2*)(ob + (size_t)(q0+m0+gid+8)*DD + c) = make_float2(o[j][2]*inv1, o[j][3]*inv1);
    }
}

// ---------------- launch ----------------
extern "C" void kernel_launch(void* const* d_in, const int* in_sizes, int n_in,
                              void* d_out, int out_size)
{
    const float* x        = (const float*)d_in[0];
    const float* emask    = (const float*)d_in[1];
    const float* ln1_w    = (const float*)d_in[2];
    const float* wq       = (const float*)d_in[3];
    const float* bq       = (const float*)d_in[4];
    const float* wk       = (const float*)d_in[5];
    const float* bk       = (const float*)d_in[6];
    const float* wv       = (const float*)d_in[7];
    const float* bv       = (const float*)d_in[8];
    const float* wo       = (const float*)d_in[9];
    const float* ln2_w    = (const float*)d_in[10];
    const float* w_gate   = (const float*)d_in[11];
    const float* w_up     = (const float*)d_in[12];
    const float* w_down   = (const float*)d_in[13];
    const float* we_gate  = (const float*)d_in[14];
    const float* we_up    = (const float*)d_in[15];
    const float* we_down  = (const float*)d_in[16];
    float* out = (float*)d_out;

    float *h,*q,*k,*v,*att,*x2,*h2,*gate,*up,*eg,*eu,*tmp;
    cudaGetSymbolAddress((void**)&h,   g_h);
    cudaGetSymbolAddress((void**)&q,   g_q);
    cudaGetSymbolAddress((void**)&k,   g_k);
    cudaGetSymbolAddress((void**)&v,   g_v);
    cudaGetSymbolAddress((void**)&att, g_att);
    cudaGetSymbolAddress((void**)&x2,  g_x2);
    cudaGetSymbolAddress((void**)&h2,  g_h2);
    cudaGetSymbolAddress((void**)&gate,g_gate);
    cudaGetSymbolAddress((void**)&up,  g_up);
    cudaGetSymbolAddress((void**)&eg,  g_eg);
    cudaGetSymbolAddress((void**)&eu,  g_eu);
    cudaGetSymbolAddress((void**)&tmp, g_tmp);

    cudaFuncSetAttribute(mgemm_kernel<0>, cudaFuncAttributeMaxDynamicSharedMemorySize, MG_SMEM);
    cudaFuncSetAttribute(mgemm_kernel<1>, cudaFuncAttributeMaxDynamicSharedMemorySize, MG_SMEM);
    cudaFuncSetAttribute(mgemm_kernel<2>, cudaFuncAttributeMaxDynamicSharedMemorySize, MG_SMEM);
    cudaFuncSetAttribute(mgemm_kernel<3>, cudaFuncAttributeMaxDynamicSharedMemorySize, MG_SMEM);
    cudaFuncSetAttribute(mgemm_kernel<4>, cudaFuncAttributeMaxDynamicSharedMemorySize, MG_SMEM);
    cudaFuncSetAttribute(flash_tc_kernel, cudaFuncAttributeMaxDynamicSharedMemorySize, FL_SMEM);

    // 1) h = rmsnorm(x)
    rmsnorm_kernel<<<NTOK, 256>>>(x, ln1_w, h);

    // 2) QKV projections (+bias)
    mgemm_kernel<1><<<dim3(8,64,1), 256, MG_SMEM>>>(h, wq, q, NTOK, 1024, 1024, 1024, bq, nullptr, nullptr, 0, 0);
    mgemm_kernel<1><<<dim3(4,64,1), 256, MG_SMEM>>>(h, wk, k, NTOK,  512, 1024,  512, bk, nullptr, nullptr, 0, 0);
    mgemm_kernel<1><<<dim3(4,64,1), 256, MG_SMEM>>>(h, wv, v, NTOK,  512, 1024,  512, bv, nullptr, nullptr, 0, 0);

    // 3) RoPE
    {
        long tq = (long)NTOK * HH  * 32;
        rope_kernel<<<(unsigned)((tq + 255) / 256), 256>>>(q, HH, tq);
        long tk = (long)NTOK * KVH * 32;
        rope_kernel<<<(unsigned)((tk + 255) / 256), 256>>>(k, KVH, tk);
    }

    // 4) attention (tf32 tensor cores)
    flash_tc_kernel<<<dim3(PP/64, HH, BB), 128, FL_SMEM>>>(q, k, v, att);

    // 5) x2 = x + att @ wo
    mgemm_kernel<2><<<dim3(8,64,1), 256, MG_SMEM>>>(att, wo, x2, NTOK, 1024, 1024, 1024, nullptr, x, nullptr, 0, 0);

    // 6) h2 = rmsnorm(x2)
    rmsnorm_kernel<<<NTOK, 256>>>(x2, ln2_w, h2);

    // 7) dense MLP: up first, then gate with fused silu*up, then down(+res)
    mgemm_kernel<0><<<dim3(32,64,1), 256, MG_SMEM>>>(h2, w_up,   up,   NTOK, 4096, 1024, 4096, nullptr, nullptr, nullptr, 0, 0);
    mgemm_kernel<3><<<dim3(32,64,1), 256, MG_SMEM>>>(h2, w_gate, gate, NTOK, 4096, 1024, 4096, nullptr, up,      nullptr, 0, 0);
    mgemm_kernel<2><<<dim3(8,64,1),  256, MG_SMEM>>>(gate, w_down, tmp, NTOK, 1024, 4096, 1024, nullptr, x2,     nullptr, 0, 0);

    // 8) experts (z-batched): eu first, then eg with fused silu*eu*mask
    mgemm_kernel<0><<<dim3(2,64,NE), 256, MG_SMEM>>>(h2, we_up,   eu, NTOK, 256, 1024, 4096,
                                                     nullptr, nullptr, nullptr, (long)1024*256, 256);
    mgemm_kernel<4><<<dim3(2,64,NE), 256, MG_SMEM>>>(h2, we_gate, eg, NTOK, 256, 1024, 4096,
                                                     nullptr, eu, emask, (long)1024*256, 256);
    // 9) out = tmp + expert_acts @ we_down
    mgemm_kernel<2><<<dim3(8,64,1), 256, MG_SMEM>>>(eg, we_down, out, NTOK, 1024, 4096, 1024, nullptr, tmp, nullptr, 0, 0);
}